// round 5
// baseline (speedup 1.0000x reference)
#include <cuda_runtime.h>
#include <math.h>

#define NB    128     // batches
#define NPTS  128     // points per batch
#define DIN   1024
#define H1D   256
#define DOUT  32
#define KCL   8
#define NTRI  8128    // 128*127/2

__device__ __forceinline__ float gelu_exact(float v) {
    // jax.nn.gelu(approximate=False): 0.5*x*(1+erf(x/sqrt(2)))
    return 0.5f * v * (1.0f + erff(v * 0.70710678118654752440f));
}
__device__ __forceinline__ int tri_base(int i) { return (i * (255 - i)) >> 1; }

// ---------------------------------------------------------------------------
// ONE fused kernel: CTA b computes the MLP for its 128 tokens, then runs the
// greedy Ward agglomeration, then writes labels (as float32 — harness output
// dtype). All state in static smem.
// ---------------------------------------------------------------------------
__global__ __launch_bounds__(256) void fused_kernel(
    const float* __restrict__ x,  const float* __restrict__ W1,
    const float* __restrict__ b1, const float* __restrict__ W2,
    const float* __restrict__ b2, float* __restrict__ out)
{
    // union buffer: phase A uses first 4096 floats as xs[32][128]; phase B = Dtri
    __shared__ float ubuf[NTRI];            // 32512 B
    __shared__ float centT[DOUT][NPTS];     // 16384 B, transposed feats/centroids
    __shared__ float wrv[8];
    __shared__ int   wri[8];
    __shared__ int   sI2, sJ2;
    __shared__ float sSi, sSj, sSQI;
    __shared__ unsigned sAlive[4];

    const int tid  = threadIdx.x;
    const int b    = blockIdx.x;
    const int lane = tid & 31;
    const int wid  = tid >> 5;
    const float INF = __int_as_float(0x7f800000);
    float* xs = ubuf;   // [32][128] during phase A

    // =============== Phase A: MLP (gelu -> @W1+b1 -> gelu -> @W2+b2) ===============
    for (int g = 0; g < 4; g++) {           // 4 groups of 32 tokens
        const int tok0 = g * 32;

        float acc[32];
#pragma unroll
        for (int t = 0; t < 32; t++) acc[t] = 0.0f;

        for (int kc = 0; kc < DIN; kc += 128) {
            for (int idx = tid; idx < 32 * 128; idx += 256) {
                int t = idx >> 7, kk = idx & 127;
                xs[idx] = gelu_exact(x[(size_t)(b * NPTS + tok0 + t) * DIN + kc + kk]);
            }
            __syncthreads();
            for (int kk = 0; kk < 128; kk++) {
                float wv = W1[(size_t)(kc + kk) * H1D + tid];   // thread = h1 column
#pragma unroll
                for (int t = 0; t < 32; t++) acc[t] = fmaf(xs[t * 128 + kk], wv, acc[t]);
            }
            __syncthreads();
        }

        float bb = b1[tid];
#pragma unroll
        for (int t = 0; t < 32; t++) acc[t] = gelu_exact(acc[t] + bb);

        // layer 2: each thread owns 4 (token, out) pairs; hidden staged in halves
        float oacc[4];
#pragma unroll
        for (int u = 0; u < 4; u++) oacc[u] = b2[(u * 256 + tid) & 31];

        for (int h = 0; h < 2; h++) {
            if ((tid >> 7) == h) {          // threads owning cols [h*128, h*128+128)
                int c = tid & 127;
#pragma unroll
                for (int t = 0; t < 32; t++) xs[t * 128 + c] = acc[t];
            }
            __syncthreads();
#pragma unroll
            for (int u = 0; u < 4; u++) {
                int lin = u * 256 + tid;
                int t = lin >> 5, o = lin & 31;
                float s = oacc[u];
                for (int j = 0; j < 128; j++)
                    s = fmaf(xs[t * 128 + j], W2[(size_t)(h * 128 + j) * DOUT + o], s);
                oacc[u] = s;
            }
            __syncthreads();
        }
#pragma unroll
        for (int u = 0; u < 4; u++) {
            int lin = u * 256 + tid;
            int t = lin >> 5, o = lin & 31;
            centT[o][tok0 + t] = oacc[u];
        }
        __syncthreads();
    }

    // =============== Phase B: greedy Ward agglomeration ===============
    float* Dtri = ubuf;
    const int a = tid;                  // threads 0..127 own point a
    const bool is_low = (tid < NPTS);

    float sq_a = 0.0f, s_a = 1.0f;
    int   lab_a = a;
    bool  alive = true;
    if (is_low) {
#pragma unroll
        for (int d = 0; d < DOUT; d++) { float c = centT[d][a]; sq_a = fmaf(c, c, sq_a); }
    }
    __syncthreads();

    // initial triangle distances (sizes all 1)
    for (int i = 0; i < NPTS - 1; i++) {
        int j = i + 1 + tid;
        if (j < NPTS) {
            float dot = 0.0f, sqi = 0.0f, sqj = 0.0f;
#pragma unroll
            for (int d = 0; d < DOUT; d++) {
                float ci = centT[d][i];   // broadcast
                float cj = centT[d][j];
                dot = fmaf(ci, cj, dot);
                sqi = fmaf(ci, ci, sqi);
                sqj = fmaf(cj, cj, sqj);
            }
            float d2 = fmaxf(sqi + sqj - 2.0f * dot, 0.0f);
            float w  = (1.0f * 1.0f) / (1.0f + 1.0f + 1e-30f);
            Dtri[tri_base(i) + j - i - 1] = w * d2;
        }
    }
    __syncthreads();

    for (int it = 0; it < NPTS - KCL; it++) {
        // --- argmin over triangle, first-occurrence tie-break (== jnp.argmin) ---
        float bv = INF;
        int   bi = NTRI;
        for (int t = tid; t < NTRI; t += 256) {     // ascending per thread
            float v = Dtri[t];
            if (v < bv) { bv = v; bi = t; }         // strict < keeps smallest index
        }
#pragma unroll
        for (int off = 16; off; off >>= 1) {
            float ov = __shfl_down_sync(0xffffffffu, bv, off);
            int   oi = __shfl_down_sync(0xffffffffu, bi, off);
            if (ov < bv || (ov == bv && oi < bi)) { bv = ov; bi = oi; }
        }
        if (lane == 0) { wrv[wid] = bv; wri[wid] = bi; }
        __syncthreads();

        if (tid == 0) {
            float fv = wrv[0]; int fi = wri[0];
#pragma unroll
            for (int w8 = 1; w8 < 8; w8++)
                if (wrv[w8] < fv || (wrv[w8] == fv && wri[w8] < fi)) { fv = wrv[w8]; fi = wri[w8]; }
            // decode flat triangle index -> (i2, j2)
            int i2 = (int)((255.0f - sqrtf(65025.0f - 8.0f * (float)fi)) * 0.5f);
            i2 = i2 < 0 ? 0 : (i2 > 126 ? 126 : i2);
            while (i2 > 0   && tri_base(i2)     > fi) i2--;
            while (i2 < 126 && tri_base(i2 + 1) <= fi) i2++;
            sI2 = i2;
            sJ2 = i2 + 1 + (fi - tri_base(i2));
        }
        __syncthreads();

        const int i2 = sI2, j2 = sJ2;
        if (a == i2) sSi = s_a;
        if (a == j2) sSj = s_a;
        __syncthreads();

        const float si = sSi, sj = sSj, snew = si + sj;
        if (tid < DOUT)
            centT[tid][i2] = (centT[tid][i2] * si + centT[tid][j2] * sj) / snew;
        if (is_low) {
            if (lab_a == j2) lab_a = i2;
            if (a == j2) { alive = false; s_a = 0.0f; }
            if (a == i2) s_a = snew;
        }
        __syncthreads();

        // sq of merged centroid (warp 0 tree-reduce)
        if (tid < 32) {
            float c = centT[lane][i2];
            float p = c * c;
#pragma unroll
            for (int off = 16; off; off >>= 1) p += __shfl_down_sync(0xffffffffu, p, off);
            if (lane == 0) sSQI = p;
        }
        __syncthreads();

        const float sqi2 = sSQI;
        if (is_low) {
            if (a == i2) sq_a = sqi2;
            if (a != i2) {
                float v;
                if (!alive) v = INF;
                else {
                    float dot = 0.0f;
#pragma unroll
                    for (int d = 0; d < DOUT; d++)
                        dot = fmaf(centT[d][i2], centT[d][a], dot);
                    float d2 = fmaxf(sqi2 + sq_a - 2.0f * dot, 0.0f);
                    float w  = (snew * s_a) / (snew + s_a + 1e-30f);
                    v = w * d2;
                }
                int lo = min(a, i2), hi = max(a, i2);
                Dtri[tri_base(lo) + hi - lo - 1] = v;
            }
            if (a != j2) {
                int lo = min(a, j2), hi = max(a, j2);
                Dtri[tri_base(lo) + hi - lo - 1] = INF;
            }
        }
        __syncthreads();
    }

    // =============== rank surviving reps (cumsum of alive) -> labels ===============
    if (is_low) {
        unsigned m = __ballot_sync(0xffffffffu, alive);
        if (lane == 0) sAlive[wid] = m;
    }
    __syncthreads();
    if (is_low) {
        const int r = lab_a, rw = r >> 5, rl = r & 31;
        int rank = 0;
#pragma unroll
        for (int w4 = 0; w4 < 4; w4++) {
            unsigned mm = sAlive[w4];
            if (w4 < rw)       rank += __popc(mm);
            else if (w4 == rw) rank += __popc(mm & ((rl == 0) ? 0u : (0xffffffffu >> (32 - rl))));
        }
        // Output dtype hypothesis: float32 (labels compared as floats).
        out[b * NPTS + a] = (float)rank;
    }
}

// ---------------------------------------------------------------------------
extern "C" void kernel_launch(void* const* d_in, const int* in_sizes, int n_in,
                              void* d_out, int out_size) {
    // Positional binding x,W1,b1,W2,b2 with size-based override (all sizes unique).
    const float* x  = (const float*)d_in[0];
    const float* W1 = (n_in > 1) ? (const float*)d_in[1] : 0;
    const float* b1 = (n_in > 2) ? (const float*)d_in[2] : 0;
    const float* W2 = (n_in > 3) ? (const float*)d_in[3] : 0;
    const float* b2 = (n_in > 4) ? (const float*)d_in[4] : 0;
    for (int i = 0; i < n_in; i++) {
        switch (in_sizes[i]) {
            case NB * NPTS * DIN: x  = (const float*)d_in[i]; break;
            case DIN * H1D:       W1 = (const float*)d_in[i]; break;
            case H1D:             b1 = (const float*)d_in[i]; break;
            case H1D * DOUT:      W2 = (const float*)d_in[i]; break;
            case DOUT:            b2 = (const float*)d_in[i]; break;
            default: break;
        }
    }
    float* out = (float*)d_out;

    fused_kernel<<<NB, 256>>>(x, W1, b1, W2, b2, out);
}

// round 6
// speedup vs baseline: 1.9025x; 1.9025x over previous
#include <cuda_runtime.h>
#include <math.h>

#define NB    128
#define NPTS  128
#define DIN   1024
#define H1D   256
#define DOUT  32
#define KCL   8
#define NTRI  8128
#define BN    16384

// feats scratch [BN, 32] fp32 (static device array — no allocation)
__device__ float g_feats[BN * DOUT];

__device__ __forceinline__ float gelu_exact(float v) {
    return 0.5f * v * (1.0f + erff(v * 0.70710678118654752440f));
}
__device__ __forceinline__ int tri_base(int i) { return (i * (255 - i)) >> 1; }

// ---- packed f32x2 helpers (per-lane IEEE fp32 FMA: bitwise == scalar fmaf) ----
__device__ __forceinline__ unsigned long long pack2(float v) {
    unsigned long long r;
    asm("mov.b64 %0, {%1, %1};" : "=l"(r) : "f"(v));
    return r;
}
__device__ __forceinline__ void fma2(unsigned long long& d, unsigned long long a, unsigned long long b) {
    asm("fma.rn.f32x2 %0, %1, %2, %3;" : "=l"(d) : "l"(a), "l"(b), "l"(d));
}
__device__ __forceinline__ float2 unpack2(unsigned long long v) {
    float2 r;
    asm("mov.b64 {%0, %1}, %2;" : "=f"(r.x), "=f"(r.y) : "l"(v));
    return r;
}

// ---------------------------------------------------------------------------
// MLP kernel: grid 512 (32 tokens/CTA), 256 threads. Thread = one H1 column,
// token-pairs packed into f32x2 accumulators. gelu(x) staged transposed
// (stride 36 floats: float4-aligned, ~conflict-free) so the inner loop does
// 8x LDS.128 + 16x FFMA2 + 1 LDG per k.
// ---------------------------------------------------------------------------
__global__ __launch_bounds__(256) void mlp_kernel(
    const float* __restrict__ x,  const float* __restrict__ W1,
    const float* __restrict__ b1, const float* __restrict__ W2,
    const float* __restrict__ b2)
{
    __shared__ __align__(16) float xs[128 * 36];   // 18 KB; reused for layer-2 staging
    const int tid  = threadIdx.x;
    const int tok0 = blockIdx.x * 32;

    unsigned long long acc2[16];
#pragma unroll
    for (int u = 0; u < 16; u++) acc2[u] = 0ull;   // (0.f, 0.f)

    for (int kc = 0; kc < DIN; kc += 128) {
        // stage gelu(x) transposed: xs[kk*36 + t]
        for (int idx = tid; idx < 32 * 128; idx += 256) {
            int t = idx >> 7, kk = idx & 127;
            xs[kk * 36 + t] = gelu_exact(x[(size_t)(tok0 + t) * DIN + kc + kk]);
        }
        __syncthreads();
#pragma unroll 4
        for (int kk = 0; kk < 128; kk++) {
            unsigned long long wv2 = pack2(W1[(size_t)(kc + kk) * H1D + tid]);
            const ulonglong2* row = (const ulonglong2*)(xs + kk * 36);
#pragma unroll
            for (int v = 0; v < 8; v++) {
                ulonglong2 f = row[v];          // tokens 4v..4v+3 (LDS.128 broadcast)
                fma2(acc2[2 * v],     f.x, wv2);
                fma2(acc2[2 * v + 1], f.y, wv2);
            }
        }
        __syncthreads();
    }

    // bias + gelu -> hidden values for this thread's column
    float h[32];
    {
        float bb = b1[tid];
#pragma unroll
        for (int u = 0; u < 16; u++) {
            float2 p = unpack2(acc2[u]);
            h[2 * u]     = gelu_exact(p.x + bb);
            h[2 * u + 1] = gelu_exact(p.y + bb);
        }
    }

    // layer 2: stage hidden in halves of 128 cols; each thread -> 4 (token,out) pairs
    float oacc[4];
#pragma unroll
    for (int u = 0; u < 4; u++) oacc[u] = b2[(u * 256 + tid) & 31];

    for (int half = 0; half < 2; half++) {
        if ((tid >> 7) == half) {
            int c = tid & 127;
#pragma unroll
            for (int t = 0; t < 32; t++) xs[t * 128 + c] = h[t];
        }
        __syncthreads();
#pragma unroll
        for (int u = 0; u < 4; u++) {
            int lin = u * 256 + tid;
            int t = lin >> 5, o = lin & 31;
            float s = oacc[u];
            for (int j = 0; j < 128; j++)
                s = fmaf(xs[t * 128 + j], W2[(size_t)(half * 128 + j) * DOUT + o], s);
            oacc[u] = s;
        }
        __syncthreads();
    }
#pragma unroll
    for (int u = 0; u < 4; u++) {
        int lin = u * 256 + tid;
        int t = lin >> 5, o = lin & 31;
        g_feats[(size_t)(tok0 + t) * DOUT + o] = oacc[u];
    }
}

// ---------------------------------------------------------------------------
// Ward kernel: one CTA per batch, 256 threads, static smem (< 48 KB + eps).
// Identical algorithm to the R5-passing fused phase B.
// ---------------------------------------------------------------------------
__global__ __launch_bounds__(256) void ward_kernel(float* __restrict__ out) {
    __shared__ float Dtri[NTRI];            // 32512 B
    __shared__ float centT[DOUT][NPTS];     // 16384 B
    __shared__ float wrv[8];
    __shared__ int   wri[8];
    __shared__ int   sI2, sJ2;
    __shared__ float sSi, sSj, sSQI;
    __shared__ unsigned sAlive[4];

    const int tid  = threadIdx.x;
    const int b    = blockIdx.x;
    const int lane = tid & 31;
    const int wid  = tid >> 5;
    const float INF = __int_as_float(0x7f800000);

    // load feats transposed
    for (int idx = tid; idx < NPTS * DOUT; idx += 256) {
        int r = idx >> 5, d = idx & 31;
        centT[d][r] = g_feats[(size_t)(b * NPTS + r) * DOUT + d];
    }
    __syncthreads();

    const int a = tid;
    const bool is_low = (tid < NPTS);
    float sq_a = 0.0f, s_a = 1.0f;
    int   lab_a = a;
    bool  alive = true;
    if (is_low) {
#pragma unroll
        for (int d = 0; d < DOUT; d++) { float c = centT[d][a]; sq_a = fmaf(c, c, sq_a); }
    }
    __syncthreads();

    // initial triangle distances (sizes all 1)
    for (int i = 0; i < NPTS - 1; i++) {
        int j = i + 1 + tid;
        if (j < NPTS) {
            float dot = 0.0f, sqi = 0.0f, sqj = 0.0f;
#pragma unroll
            for (int d = 0; d < DOUT; d++) {
                float ci = centT[d][i];
                float cj = centT[d][j];
                dot = fmaf(ci, cj, dot);
                sqi = fmaf(ci, ci, sqi);
                sqj = fmaf(cj, cj, sqj);
            }
            float d2 = fmaxf(sqi + sqj - 2.0f * dot, 0.0f);
            float w  = (1.0f * 1.0f) / (1.0f + 1.0f + 1e-30f);
            Dtri[tri_base(i) + j - i - 1] = w * d2;
        }
    }
    __syncthreads();

    for (int it = 0; it < NPTS - KCL; it++) {
        // argmin, first-occurrence tie-break (== jnp.argmin)
        float bv = INF;
        int   bi = NTRI;
        for (int t = tid; t < NTRI; t += 256) {
            float v = Dtri[t];
            if (v < bv) { bv = v; bi = t; }
        }
#pragma unroll
        for (int off = 16; off; off >>= 1) {
            float ov = __shfl_down_sync(0xffffffffu, bv, off);
            int   oi = __shfl_down_sync(0xffffffffu, bi, off);
            if (ov < bv || (ov == bv && oi < bi)) { bv = ov; bi = oi; }
        }
        if (lane == 0) { wrv[wid] = bv; wri[wid] = bi; }
        __syncthreads();

        if (tid == 0) {
            float fv = wrv[0]; int fi = wri[0];
#pragma unroll
            for (int w8 = 1; w8 < 8; w8++)
                if (wrv[w8] < fv || (wrv[w8] == fv && wri[w8] < fi)) { fv = wrv[w8]; fi = wri[w8]; }
            int i2 = (int)((255.0f - sqrtf(65025.0f - 8.0f * (float)fi)) * 0.5f);
            i2 = i2 < 0 ? 0 : (i2 > 126 ? 126 : i2);
            while (i2 > 0   && tri_base(i2)     > fi) i2--;
            while (i2 < 126 && tri_base(i2 + 1) <= fi) i2++;
            sI2 = i2;
            sJ2 = i2 + 1 + (fi - tri_base(i2));
        }
        __syncthreads();

        const int i2 = sI2, j2 = sJ2;
        if (a == i2) sSi = s_a;
        if (a == j2) sSj = s_a;
        __syncthreads();

        const float si = sSi, sj = sSj, snew = si + sj;
        if (tid < DOUT)
            centT[tid][i2] = (centT[tid][i2] * si + centT[tid][j2] * sj) / snew;
        if (is_low) {
            if (lab_a == j2) lab_a = i2;
            if (a == j2) { alive = false; s_a = 0.0f; }
            if (a == i2) s_a = snew;
        }
        __syncthreads();

        if (tid < 32) {
            float c = centT[lane][i2];
            float p = c * c;
#pragma unroll
            for (int off = 16; off; off >>= 1) p += __shfl_down_sync(0xffffffffu, p, off);
            if (lane == 0) sSQI = p;
        }
        __syncthreads();

        const float sqi2 = sSQI;
        if (is_low) {
            if (a == i2) sq_a = sqi2;
            if (a != i2) {
                float v;
                if (!alive) v = INF;
                else {
                    float dot = 0.0f;
#pragma unroll
                    for (int d = 0; d < DOUT; d++)
                        dot = fmaf(centT[d][i2], centT[d][a], dot);
                    float d2 = fmaxf(sqi2 + sq_a - 2.0f * dot, 0.0f);
                    float w  = (snew * s_a) / (snew + s_a + 1e-30f);
                    v = w * d2;
                }
                int lo = min(a, i2), hi = max(a, i2);
                Dtri[tri_base(lo) + hi - lo - 1] = v;
            }
            if (a != j2) {
                int lo = min(a, j2), hi = max(a, j2);
                Dtri[tri_base(lo) + hi - lo - 1] = INF;
            }
        }
        __syncthreads();
    }

    if (is_low) {
        unsigned m = __ballot_sync(0xffffffffu, alive);
        if (lane == 0) sAlive[wid] = m;
    }
    __syncthreads();
    if (is_low) {
        const int r = lab_a, rw = r >> 5, rl = r & 31;
        int rank = 0;
#pragma unroll
        for (int w4 = 0; w4 < 4; w4++) {
            unsigned mm = sAlive[w4];
            if (w4 < rw)       rank += __popc(mm);
            else if (w4 == rw) rank += __popc(mm & ((rl == 0) ? 0u : (0xffffffffu >> (32 - rl))));
        }
        out[b * NPTS + a] = (float)rank;   // float32 output dtype
    }
}

// ---------------------------------------------------------------------------
extern "C" void kernel_launch(void* const* d_in, const int* in_sizes, int n_in,
                              void* d_out, int out_size) {
    const float* x  = (const float*)d_in[0];
    const float* W1 = (n_in > 1) ? (const float*)d_in[1] : 0;
    const float* b1 = (n_in > 2) ? (const float*)d_in[2] : 0;
    const float* W2 = (n_in > 3) ? (const float*)d_in[3] : 0;
    const float* b2 = (n_in > 4) ? (const float*)d_in[4] : 0;
    for (int i = 0; i < n_in; i++) {
        switch (in_sizes[i]) {
            case BN * DIN:   x  = (const float*)d_in[i]; break;
            case DIN * H1D:  W1 = (const float*)d_in[i]; break;
            case H1D:        b1 = (const float*)d_in[i]; break;
            case H1D * DOUT: W2 = (const float*)d_in[i]; break;
            case DOUT:       b2 = (const float*)d_in[i]; break;
            default: break;
        }
    }
    float* out = (float*)d_out;

    mlp_kernel<<<BN / 32, 256>>>(x, W1, b1, W2, b2);
    ward_kernel<<<NB, 256>>>(out);
}

// round 7
// speedup vs baseline: 2.9988x; 1.5762x over previous
#include <cuda_runtime.h>
#include <math.h>

#define NB    128
#define NPTS  128
#define DIN   1024
#define H1D   256
#define DOUT  32
#define KCL   8
#define NTRI  8128
#define BN    16384

__device__ float g_feats[BN * DOUT];   // static scratch, no allocation

__device__ __forceinline__ float gelu_exact(float v) {
    return 0.5f * v * (1.0f + erff(v * 0.70710678118654752440f));
}
__device__ __forceinline__ int tri_base(int i) { return (i * (255 - i)) >> 1; }

// packed f32x2 helpers (per-lane IEEE fp32 FMA, bitwise == scalar fmaf)
__device__ __forceinline__ unsigned long long pack2(float v) {
    unsigned long long r;
    asm("mov.b64 %0, {%1, %1};" : "=l"(r) : "f"(v));
    return r;
}
__device__ __forceinline__ void fma2(unsigned long long& d, unsigned long long a, unsigned long long b) {
    asm("fma.rn.f32x2 %0, %1, %2, %3;" : "=l"(d) : "l"(a), "l"(b), "l"(d));
}
__device__ __forceinline__ float2 unpack2(unsigned long long v) {
    float2 r;
    asm("mov.b64 {%0, %1}, %2;" : "=f"(r.x), "=f"(r.y) : "l"(v));
    return r;
}

// ---------------------------------------------------------------------------
// MLP: grid 512 (32 tokens/CTA), 256 threads.
// Thread = 16 tokens (grp = tid>>7) x 2 hidden cols (cp = tid&127, cols 2cp,2cp+1).
// Accumulators: 16 x f32x2 = 32 regs. Per kk: 1 LDG.64 + 4 LDS.128 + 16 FFMA2.
// ---------------------------------------------------------------------------
__global__ __launch_bounds__(256) void mlp_kernel(
    const float* __restrict__ x,  const float* __restrict__ W1,
    const float* __restrict__ b1, const float* __restrict__ W2,
    const float* __restrict__ b2)
{
    __shared__ __align__(16) float xs[128 * 36];   // 18 KB, reused for layer 2
    const int tid  = threadIdx.x;
    const int tok0 = blockIdx.x * 32;
    const int grp  = tid >> 7;      // token group: tokens [16*grp, 16*grp+16)
    const int cp   = tid & 127;     // column pair: cols 2cp, 2cp+1

    unsigned long long acc[16];     // acc[c*8+u] = (tok 2u, 2u+1) for col 2cp+c
#pragma unroll
    for (int u = 0; u < 16; u++) acc[u] = 0ull;

    for (int kc = 0; kc < DIN; kc += 128) {
        for (int idx = tid; idx < 32 * 128; idx += 256) {
            int t = idx >> 7, kk = idx & 127;
            xs[kk * 36 + t] = gelu_exact(x[(size_t)(tok0 + t) * DIN + kc + kk]);
        }
        __syncthreads();
#pragma unroll 4
        for (int kk = 0; kk < 128; kk++) {
            float2 wv = *(const float2*)(W1 + (size_t)(kc + kk) * H1D + 2 * cp);
            unsigned long long w0 = pack2(wv.x), w1 = pack2(wv.y);
            const ulonglong2* row = (const ulonglong2*)(xs + kk * 36 + grp * 16);
#pragma unroll
            for (int v = 0; v < 4; v++) {
                ulonglong2 f = row[v];                 // tokens 4v..4v+3 (broadcast)
                fma2(acc[2 * v],         f.x, w0);
                fma2(acc[2 * v + 1],     f.y, w0);
                fma2(acc[8 + 2 * v],     f.x, w1);
                fma2(acc[8 + 2 * v + 1], f.y, w1);
            }
        }
        __syncthreads();
    }

    // bias + gelu -> h0/h1: my 16 tokens for cols 2cp, 2cp+1
    float h0[16], h1[16];
    {
        float bb0 = b1[2 * cp], bb1 = b1[2 * cp + 1];
#pragma unroll
        for (int u = 0; u < 8; u++) {
            float2 p0 = unpack2(acc[u]);
            h0[2 * u]     = gelu_exact(p0.x + bb0);
            h0[2 * u + 1] = gelu_exact(p0.y + bb0);
            float2 p1 = unpack2(acc[8 + u]);
            h1[2 * u]     = gelu_exact(p1.x + bb1);
            h1[2 * u + 1] = gelu_exact(p1.y + bb1);
        }
    }

    // layer 2: stage hidden by col-halves of 128; thread -> 4 (token,out) pairs
    float oacc[4];
#pragma unroll
    for (int u = 0; u < 4; u++) oacc[u] = b2[(u * 256 + tid) & 31];

    for (int half = 0; half < 2; half++) {
        if ((cp >> 6) == half) {
            int c0 = 2 * cp - half * 128;
#pragma unroll
            for (int t = 0; t < 16; t++) {
                xs[(grp * 16 + t) * 128 + c0]     = h0[t];
                xs[(grp * 16 + t) * 128 + c0 + 1] = h1[t];
            }
        }
        __syncthreads();
#pragma unroll
        for (int u = 0; u < 4; u++) {
            int lin = u * 256 + tid;
            int t = lin >> 5, o = lin & 31;
            float s = oacc[u];
            for (int j = 0; j < 128; j++)
                s = fmaf(xs[t * 128 + j], W2[(size_t)(half * 128 + j) * DOUT + o], s);
            oacc[u] = s;
        }
        __syncthreads();
    }
#pragma unroll
    for (int u = 0; u < 4; u++) {
        int lin = u * 256 + tid;
        int t = lin >> 5, o = lin & 31;
        g_feats[(size_t)(tok0 + t) * DOUT + o] = oacc[u];
    }
}

// ---------------------------------------------------------------------------
// Ward: one CTA/batch, 256 threads. 4 barriers per merge; sizes/sq in smem;
// warp 0 fuses centroid update + sq reduce + size updates; float4 argmin.
// ---------------------------------------------------------------------------
__global__ __launch_bounds__(256) void ward_kernel(float* __restrict__ out) {
    __shared__ __align__(16) float Dtri[NTRI];   // 32512 B
    __shared__ float centT[DOUT][NPTS];          // 16384 B
    __shared__ float szs[NPTS], sqv[NPTS];
    __shared__ float wrv[8];
    __shared__ int   wri[8];
    __shared__ int   sI2, sJ2;
    __shared__ unsigned sAlive[4];

    const int tid  = threadIdx.x;
    const int b    = blockIdx.x;
    const int lane = tid & 31;
    const int wid  = tid >> 5;
    const float INF = __int_as_float(0x7f800000);

    // load feats transposed
    for (int idx = tid; idx < NPTS * DOUT; idx += 256) {
        int r = idx >> 5, d = idx & 31;
        centT[d][r] = g_feats[(size_t)(b * NPTS + r) * DOUT + d];
    }
    if (tid < NPTS) szs[tid] = 1.0f;
    __syncthreads();
    if (tid < NPTS) {
        float s = 0.0f;
#pragma unroll
        for (int d = 0; d < DOUT; d++) { float c = centT[d][tid]; s = fmaf(c, c, s); }
        sqv[tid] = s;
    }
    int lab = tid;   // valid for tid < 128
    __syncthreads();

    // initial triangle distances (sizes all 1), flat-index balanced
    for (int p = 0; p < 32; p++) {
        int t = tid + p * 256;
        if (t < NTRI) {
            int i = (int)((255.0f - sqrtf(65025.0f - 8.0f * (float)t)) * 0.5f);
            i = i < 0 ? 0 : (i > 126 ? 126 : i);
            while (i > 0   && tri_base(i)     > t) i--;
            while (i < 126 && tri_base(i + 1) <= t) i++;
            int j = i + 1 + (t - tri_base(i));
            float dot = 0.0f, sqi = 0.0f, sqj = 0.0f;
#pragma unroll
            for (int d = 0; d < DOUT; d++) {
                float ci = centT[d][i];
                float cj = centT[d][j];
                dot = fmaf(ci, cj, dot);
                sqi = fmaf(ci, ci, sqi);
                sqj = fmaf(cj, cj, sqj);
            }
            float d2 = fmaxf(sqi + sqj - 2.0f * dot, 0.0f);
            float w  = (1.0f * 1.0f) / (1.0f + 1.0f + 1e-30f);
            Dtri[t] = w * d2;
        }
    }
    __syncthreads();

    for (int it = 0; it < NPTS - KCL; it++) {
        // argmin (float4), first-occurrence tie-break == jnp.argmin
        float bv = INF;
        int   bi = NTRI;
        const float4* D4 = (const float4*)Dtri;
#pragma unroll
        for (int p = 0; p < 8; p++) {
            int q = tid + p * 256;
            if (q < NTRI / 4) {
                float4 v = D4[q];
                int base = q * 4;                      // ascending per thread
                if (v.x < bv) { bv = v.x; bi = base; }
                if (v.y < bv) { bv = v.y; bi = base + 1; }
                if (v.z < bv) { bv = v.z; bi = base + 2; }
                if (v.w < bv) { bv = v.w; bi = base + 3; }
            }
        }
#pragma unroll
        for (int off = 16; off; off >>= 1) {
            float ov = __shfl_down_sync(0xffffffffu, bv, off);
            int   oi = __shfl_down_sync(0xffffffffu, bi, off);
            if (ov < bv || (ov == bv && oi < bi)) { bv = ov; bi = oi; }
        }
        if (lane == 0) { wrv[wid] = bv; wri[wid] = bi; }
        __syncthreads();   // B1

        if (tid == 0) {
            float fv = wrv[0]; int fi = wri[0];
#pragma unroll
            for (int w8 = 1; w8 < 8; w8++)
                if (wrv[w8] < fv || (wrv[w8] == fv && wri[w8] < fi)) { fv = wrv[w8]; fi = wri[w8]; }
            int i2 = (int)((255.0f - sqrtf(65025.0f - 8.0f * (float)fi)) * 0.5f);
            i2 = i2 < 0 ? 0 : (i2 > 126 ? 126 : i2);
            while (i2 > 0   && tri_base(i2)     > fi) i2--;
            while (i2 < 126 && tri_base(i2 + 1) <= fi) i2++;
            sI2 = i2;
            sJ2 = i2 + 1 + (fi - tri_base(i2));
        }
        __syncthreads();   // B2

        const int i2 = sI2, j2 = sJ2;
        if (tid < 32) {    // warp 0: centroid + sq + sizes, fused
            float si = szs[i2], sj = szs[j2], snew = si + sj;
            float nc = (centT[tid][i2] * si + centT[tid][j2] * sj) / snew;
            centT[tid][i2] = nc;
            float p = nc * nc;
#pragma unroll
            for (int off = 16; off; off >>= 1) p += __shfl_down_sync(0xffffffffu, p, off);
            if (tid == 0) { sqv[i2] = p; szs[i2] = snew; szs[j2] = 0.0f; }
        }
        if (tid < NPTS && lab == j2) lab = i2;
        __syncthreads();   // B3

        if (tid < NPTS) {
            const int a = tid;
            float sa = szs[a];
            if (a != i2) {
                float v;
                if (sa == 0.0f) v = INF;
                else {
                    float snew = szs[i2];
                    float dot = 0.0f;
#pragma unroll
                    for (int d = 0; d < DOUT; d++)
                        dot = fmaf(centT[d][i2], centT[d][a], dot);
                    float d2 = fmaxf(sqv[i2] + sqv[a] - 2.0f * dot, 0.0f);
                    float w  = (snew * sa) / (snew + sa + 1e-30f);
                    v = w * d2;
                }
                int lo = min(a, i2), hi = max(a, i2);
                Dtri[tri_base(lo) + hi - lo - 1] = v;
            }
            if (a != j2) {
                int lo = min(a, j2), hi = max(a, j2);
                Dtri[tri_base(lo) + hi - lo - 1] = INF;
            }
        }
        __syncthreads();   // B4
    }

    // rank surviving representatives -> labels
    if (tid < NPTS) {
        unsigned m = __ballot_sync(0xffffffffu, szs[tid] > 0.0f);
        if (lane == 0) sAlive[wid] = m;
    }
    __syncthreads();
    if (tid < NPTS) {
        const int r = lab, rw = r >> 5, rl = r & 31;
        int rank = 0;
#pragma unroll
        for (int w4 = 0; w4 < 4; w4++) {
            unsigned mm = sAlive[w4];
            if (w4 < rw)       rank += __popc(mm);
            else if (w4 == rw) rank += __popc(mm & ((rl == 0) ? 0u : (0xffffffffu >> (32 - rl))));
        }
        out[b * NPTS + tid] = (float)rank;   // float32 output dtype
    }
}

// ---------------------------------------------------------------------------
extern "C" void kernel_launch(void* const* d_in, const int* in_sizes, int n_in,
                              void* d_out, int out_size) {
    const float* x  = (const float*)d_in[0];
    const float* W1 = (n_in > 1) ? (const float*)d_in[1] : 0;
    const float* b1 = (n_in > 2) ? (const float*)d_in[2] : 0;
    const float* W2 = (n_in > 3) ? (const float*)d_in[3] : 0;
    const float* b2 = (n_in > 4) ? (const float*)d_in[4] : 0;
    for (int i = 0; i < n_in; i++) {
        switch (in_sizes[i]) {
            case BN * DIN:   x  = (const float*)d_in[i]; break;
            case DIN * H1D:  W1 = (const float*)d_in[i]; break;
            case H1D:        b1 = (const float*)d_in[i]; break;
            case H1D * DOUT: W2 = (const float*)d_in[i]; break;
            case DOUT:       b2 = (const float*)d_in[i]; break;
            default: break;
        }
    }
    float* out = (float*)d_out;

    mlp_kernel<<<BN / 32, 256>>>(x, W1, b1, W2, b2);
    ward_kernel<<<NB, 256>>>(out);
}